// round 1
// baseline (speedup 1.0000x reference)
#include <cuda_runtime.h>
#include <math.h>

// ---------------------------------------------------------------------------
// Problem constants
// ---------------------------------------------------------------------------
constexpr int Bn = 8, Cc = 96, Dd = 8, Hh = 32, Ww = 32;
constexpr int HW = Hh * Ww;          // 1024
constexpr int DIM = Cc * Dd;         // 768
constexpr int NH = 4;
constexpr int DHd = DIM / NH;        // 192
constexpr int SEQROWS = Bn * HW;     // 8192
constexpr int BH = Bn * NH;          // 32

// ---------------------------------------------------------------------------
// Scratch (device globals -- no allocations allowed)
// ---------------------------------------------------------------------------
__device__ float g_t[Bn * HW * DIM];                    // permuted input + pos
__device__ float g_q[Bn * NH * HW * DHd];
__device__ float g_k[Bn * NH * HW * DHd];
__device__ float g_v[Bn * NH * HW * DHd];
__device__ float g_attn[(size_t)Bn * NH * HW * HW];     // 134 MB
__device__ float g_om[Bn * HW * DIM];                   // merged attn out
__device__ float g_proj[Bn * HW * DIM];                 // proj output
__device__ float g_y[Bn * Cc * Dd * HW];                // residual sum, x-layout
__device__ float g_z[Bn * Cc * Dd * HW];                // depthwise conv out

// ---------------------------------------------------------------------------
// Kernel 1: b c d h w -> b (h w) (c d), + pos_embed
// ---------------------------------------------------------------------------
__global__ void permute_add_pos(const float* __restrict__ x,
                                const float* __restrict__ pos) {
    int i = blockIdx.x * 256 + threadIdx.x;
    if (i >= Bn * HW * DIM) return;
    int cd = i % DIM;
    int t  = i / DIM;
    int hw = t % HW;
    int b  = t / HW;
    int c = cd >> 3;        // /Dd
    int d = cd & 7;
    int xidx = ((b * Cc + c) * Dd + d) * HW + hw;
    g_t[i] = x[xidx] + pos[hw * DIM + cd];
}

// ---------------------------------------------------------------------------
// Generic 64x64x16 tiled SGEMM, 256 threads, 4x4 microtile.
// MODE 0: QKV   C[8192,2304] = t @ qkv_w^T, scatter to q/k/v
// MODE 1: ATTN  per z in [0,32): C[1024,1024] = q_z @ k_z^T
// MODE 2: O     per z: C[1024,192] = attn_z @ v_z (NN), merged-head store
// MODE 3: PROJ  C[8192,768] = o_m @ proj_w^T + bias
// ---------------------------------------------------------------------------
template <int MODE>
__launch_bounds__(256)
__global__ void gemm64(const float* __restrict__ W,
                       const float* __restrict__ bias) {
    __shared__ __align__(16) float As[16][68];
    __shared__ __align__(16) float Bs[16][68];

    const int tid = threadIdx.x;
    const int n0 = blockIdx.x * 64;
    const int m0 = blockIdx.y * 64;
    const int z  = blockIdx.z;

    const float* A;
    const float* Bp;
    int lda, ldb, K;
    if constexpr (MODE == 0) { A = g_t;                    Bp = W;                    lda = 768;  ldb = 768; K = 768; }
    if constexpr (MODE == 1) { A = g_q + z * (HW * DHd);   Bp = g_k + z * (HW * DHd); lda = 192;  ldb = 192; K = 192; }
    if constexpr (MODE == 2) { A = g_attn + (size_t)z * (HW * HW); Bp = g_v + z * (HW * DHd); lda = 1024; ldb = 192; K = 1024; }
    if constexpr (MODE == 3) { A = g_om;                   Bp = W;                    lda = 768;  ldb = 768; K = 768; }

    constexpr bool NT = (MODE != 2);

    const int tn = tid & 15;
    const int tm = tid >> 4;

    float acc[4][4];
#pragma unroll
    for (int i = 0; i < 4; i++)
#pragma unroll
        for (int j = 0; j < 4; j++) acc[i][j] = 0.f;

    for (int k0 = 0; k0 < K; k0 += 16) {
        // load A tile (A is [M][K], K-contiguous)
        {
            int kk = tid & 15;
            int mm = tid >> 4;
#pragma unroll
            for (int r = 0; r < 4; r++)
                As[kk][mm + 16 * r] = A[(m0 + mm + 16 * r) * lda + k0 + kk];
        }
        // load B tile
        if constexpr (NT) {
            int kk = tid & 15;
            int nn = tid >> 4;
#pragma unroll
            for (int r = 0; r < 4; r++)
                Bs[kk][nn + 16 * r] = Bp[(n0 + nn + 16 * r) * ldb + k0 + kk];
        } else {
            int nn  = tid & 63;
            int kkb = tid >> 6;
#pragma unroll
            for (int r = 0; r < 4; r++)
                Bs[kkb + 4 * r][nn] = Bp[(k0 + kkb + 4 * r) * ldb + n0 + nn];
        }
        __syncthreads();

#pragma unroll
        for (int kk = 0; kk < 16; kk++) {
            float4 af = *reinterpret_cast<const float4*>(&As[kk][tm * 4]);
            float4 bf = *reinterpret_cast<const float4*>(&Bs[kk][tn * 4]);
            float a[4] = {af.x, af.y, af.z, af.w};
            float b[4] = {bf.x, bf.y, bf.z, bf.w};
#pragma unroll
            for (int i = 0; i < 4; i++)
#pragma unroll
                for (int j = 0; j < 4; j++) acc[i][j] += a[i] * b[j];
        }
        __syncthreads();
    }

    // epilogue
#pragma unroll
    for (int i = 0; i < 4; i++) {
        int m = m0 + tm * 4 + i;
#pragma unroll
        for (int j = 0; j < 4; j++) {
            int n = n0 + tn * 4 + j;
            float v = acc[i][j];
            if constexpr (MODE == 0) {
                int s   = n / 768;
                int rem = n - s * 768;
                int h   = rem / 192;
                int dh  = rem - h * 192;
                int b   = m >> 10;
                int seq = m & 1023;
                float* dst = (s == 0) ? g_q : (s == 1) ? g_k : g_v;
                dst[((b * NH + h) * HW + seq) * DHd + dh] = v;
            }
            if constexpr (MODE == 1) {
                g_attn[(size_t)z * (HW * HW) + m * HW + n] = v;
            }
            if constexpr (MODE == 2) {
                int b = z >> 2, h = z & 3;
                g_om[(b * HW + m) * DIM + h * DHd + n] = v;
            }
            if constexpr (MODE == 3) {
                g_proj[m * DIM + n] = v + bias[n];
            }
        }
    }
}

// ---------------------------------------------------------------------------
// L2 normalize q and k over the sequence axis (per (b,h,d) column)
// grid 64 (32 for q, 32 for k), 192 threads
// ---------------------------------------------------------------------------
__global__ void l2norm_seq() {
    int bh = blockIdx.x & 31;
    float* p = (blockIdx.x < 32 ? g_q : g_k) + bh * (HW * DHd);
    int d = threadIdx.x;            // 0..191
    float ss = 0.f;
#pragma unroll 4
    for (int n = 0; n < HW; n++) {
        float v = p[n * DHd + d];
        ss += v * v;
    }
    float inv = 1.f / fmaxf(sqrtf(ss), 1e-12f);
#pragma unroll 4
    for (int n = 0; n < HW; n++) p[n * DHd + d] *= inv;
}

// ---------------------------------------------------------------------------
// Softmax per row (with temperature), rows = 32768, 256 threads
// ---------------------------------------------------------------------------
__global__ void softmax_rows(const float* __restrict__ temp) {
    __shared__ float red[256];
    int row = blockIdx.x;
    int tid = threadIdx.x;
    float* p = g_attn + (size_t)row * HW;
    int h = (row >> 10) & 3;
    float ts = temp[h];

    float v[4];
    float mx = -1e30f;
#pragma unroll
    for (int j = 0; j < 4; j++) {
        v[j] = p[tid + 256 * j] * ts;
        mx = fmaxf(mx, v[j]);
    }
    red[tid] = mx; __syncthreads();
    for (int s = 128; s > 0; s >>= 1) {
        if (tid < s) red[tid] = fmaxf(red[tid], red[tid + s]);
        __syncthreads();
    }
    mx = red[0]; __syncthreads();

    float sum = 0.f;
#pragma unroll
    for (int j = 0; j < 4; j++) {
        v[j] = expf(v[j] - mx);
        sum += v[j];
    }
    red[tid] = sum; __syncthreads();
    for (int s = 128; s > 0; s >>= 1) {
        if (tid < s) red[tid] += red[tid + s];
        __syncthreads();
    }
    float inv = 1.f / red[0];
#pragma unroll
    for (int j = 0; j < 4; j++) p[tid + 256 * j] = v[j] * inv;
}

// ---------------------------------------------------------------------------
// LayerNorm (over DIM) + residual, restore to b c d h w layout -> g_y
// grid 8192 rows, 256 threads (3 elems each)
// ---------------------------------------------------------------------------
__global__ void ln_residual(const float* __restrict__ x,
                            const float* __restrict__ gamma,
                            const float* __restrict__ beta) {
    __shared__ float red[256];
    int row = blockIdx.x;
    int tid = threadIdx.x;
    const float* base = g_proj + row * DIM;

    float v[3];
    float s = 0.f;
#pragma unroll
    for (int j = 0; j < 3; j++) {
        v[j] = base[tid + 256 * j];
        s += v[j];
    }
    red[tid] = s; __syncthreads();
    for (int st = 128; st > 0; st >>= 1) {
        if (tid < st) red[tid] += red[tid + st];
        __syncthreads();
    }
    float mu = red[0] * (1.f / DIM); __syncthreads();

    float s2 = 0.f;
#pragma unroll
    for (int j = 0; j < 3; j++) {
        float d = v[j] - mu;
        s2 += d * d;
    }
    red[tid] = s2; __syncthreads();
    for (int st = 128; st > 0; st >>= 1) {
        if (tid < st) red[tid] += red[tid + st];
        __syncthreads();
    }
    float rstd = rsqrtf(red[0] * (1.f / DIM) + 1e-5f);

    int b = row >> 10, hw = row & 1023;
#pragma unroll
    for (int j = 0; j < 3; j++) {
        int cd = tid + 256 * j;
        float val = (v[j] - mu) * rstd * gamma[cd] + beta[cd];
        int c = cd >> 3, d = cd & 7;
        int idx = ((b * Cc + c) * Dd + d) * HW + hw;
        g_y[idx] = val + x[idx];
    }
}

// ---------------------------------------------------------------------------
// Depthwise 3x3x3 conv (pad 1) on g_y -> g_z. grid = B*C*D, block 1024 (32x32)
// ---------------------------------------------------------------------------
__global__ __launch_bounds__(1024) void dwconv(const float* __restrict__ dw_w,
                                               const float* __restrict__ dw_b) {
    __shared__ float tile[3][34][34];
    __shared__ float wsh[27];
    int bcd = blockIdx.x;
    int d  = bcd & 7;
    int bc = bcd >> 3;
    int c  = bc % Cc;
    int tid = threadIdx.x;

    if (tid < 27) wsh[tid] = dw_w[c * 27 + tid];

    for (int idx = tid; idx < 3 * 34 * 34; idx += 1024) {
        int pl = idx / 1156;
        int r  = (idx - pl * 1156) / 34;
        int cc = idx - pl * 1156 - r * 34;
        int dd = d - 1 + pl, hh = r - 1, ww = cc - 1;
        float val = 0.f;
        if (dd >= 0 && dd < Dd && hh >= 0 && hh < Hh && ww >= 0 && ww < Ww)
            val = g_y[(bc * Dd + dd) * HW + hh * Ww + ww];
        tile[pl][r][cc] = val;
    }
    __syncthreads();

    int h = tid >> 5, w = tid & 31;
    float s = 0.f;
#pragma unroll
    for (int pl = 0; pl < 3; pl++)
#pragma unroll
        for (int i = 0; i < 3; i++)
#pragma unroll
            for (int j = 0; j < 3; j++)
                s += tile[pl][h + i][w + j] * wsh[pl * 9 + i * 3 + j];
    g_z[bcd * HW + tid] = s + dw_b[c];
}

// ---------------------------------------------------------------------------
// Pointwise 96x96 conv + final residual: out = y + (W @ z + b)
// grid (64, 8), 128 threads; each thread owns one spatial position, all co.
// ---------------------------------------------------------------------------
__global__ __launch_bounds__(128) void pwconv(const float* __restrict__ pw_w,
                                              const float* __restrict__ pw_b,
                                              float* __restrict__ out) {
    __shared__ float wsh[Cc * Cc];   // 36 KB
    int b = blockIdx.y;
    int pos = blockIdx.x * 128 + threadIdx.x;
    constexpr int SP = Dd * HW;      // 8192

    for (int i = threadIdx.x; i < Cc * Cc; i += 128) wsh[i] = pw_w[i];
    __syncthreads();

    float acc[Cc];
#pragma unroll
    for (int co = 0; co < Cc; co++) acc[co] = 0.f;

    const float* zb = g_z + b * Cc * SP + pos;
    for (int ci = 0; ci < Cc; ci++) {
        float zv = zb[ci * SP];
#pragma unroll
        for (int co = 0; co < Cc; co++) acc[co] += zv * wsh[co * Cc + ci];
    }

    const float* yb = g_y + b * Cc * SP + pos;
    float* ob = out + b * Cc * SP + pos;
#pragma unroll
    for (int co = 0; co < Cc; co++)
        ob[co * SP] = yb[co * SP] + acc[co] + pw_b[co];
}

// ---------------------------------------------------------------------------
// Launch
// ---------------------------------------------------------------------------
extern "C" void kernel_launch(void* const* d_in, const int* in_sizes, int n_in,
                              void* d_out, int out_size) {
    const float* x      = (const float*)d_in[0];
    const float* pos    = (const float*)d_in[1];
    const float* qkv_w  = (const float*)d_in[2];
    const float* proj_w = (const float*)d_in[3];
    const float* proj_b = (const float*)d_in[4];
    const float* temp   = (const float*)d_in[5];
    const float* ln_g   = (const float*)d_in[6];
    const float* ln_b   = (const float*)d_in[7];
    const float* dw_w   = (const float*)d_in[8];
    const float* dw_b   = (const float*)d_in[9];
    const float* pw_w   = (const float*)d_in[10];
    const float* pw_b   = (const float*)d_in[11];
    float* out = (float*)d_out;

    permute_add_pos<<<(Bn * HW * DIM + 255) / 256, 256>>>(x, pos);
    gemm64<0><<<dim3(2304 / 64, SEQROWS / 64, 1), 256>>>(qkv_w, nullptr);
    l2norm_seq<<<64, 192>>>();
    gemm64<1><<<dim3(HW / 64, HW / 64, BH), 256>>>(nullptr, nullptr);
    softmax_rows<<<BH * HW, 256>>>(temp);
    gemm64<2><<<dim3(DHd / 64, HW / 64, BH), 256>>>(nullptr, nullptr);
    gemm64<3><<<dim3(DIM / 64, SEQROWS / 64, 1), 256>>>(proj_w, proj_b);
    ln_residual<<<SEQROWS, 256>>>(x, ln_g, ln_b);
    dwconv<<<Bn * Cc * Dd, 1024>>>(dw_w, dw_b);
    pwconv<<<dim3(64, Bn, 1), 128>>>(pw_w, pw_b, out);
}

// round 3
// speedup vs baseline: 2.0921x; 2.0921x over previous
#include <cuda_runtime.h>
#include <math.h>
#include <stdint.h>

// ---------------------------------------------------------------------------
// Problem constants
// ---------------------------------------------------------------------------
constexpr int Bn = 8, Cc = 96, Dd = 8, Hh = 32, Ww = 32;
constexpr int HW = Hh * Ww;          // 1024
constexpr int DIM = Cc * Dd;         // 768
constexpr int NH = 4;
constexpr int DHd = DIM / NH;        // 192
constexpr int SEQROWS = Bn * HW;     // 8192
constexpr int BH = Bn * NH;          // 32

// ---------------------------------------------------------------------------
// Scratch (device globals -- no allocations allowed)
// ---------------------------------------------------------------------------
__device__ float g_t[SEQROWS * DIM];
__device__ float g_q[BH * HW * DHd];
__device__ float g_k[BH * HW * DHd];
__device__ float g_vt[BH * DHd * HW];                   // V transposed: [z][dh][seq]
__device__ float g_attn[(size_t)BH * HW * HW];          // 134 MB
__device__ float g_om[SEQROWS * DIM];
__device__ float g_proj[SEQROWS * DIM];
__device__ float g_y[Bn * Cc * Dd * HW];
__device__ float g_z[Bn * Cc * Dd * HW];

// ---------------------------------------------------------------------------
// Helpers (baseline PTX only -- no arch-'a' instructions)
// ---------------------------------------------------------------------------
__device__ __forceinline__ uint32_t f2tf(float x) {
    uint32_t r; asm("cvt.rna.tf32.f32 %0, %1;" : "=r"(r) : "f"(x)); return r;
}
__device__ __forceinline__ void mma_tf32(float* d, const uint32_t* a,
                                         const uint32_t* b) {
    asm volatile(
        "mma.sync.aligned.m16n8k8.row.col.f32.tf32.tf32.f32 "
        "{%0,%1,%2,%3}, {%4,%5,%6,%7}, {%8,%9}, {%0,%1,%2,%3};"
        : "+f"(d[0]), "+f"(d[1]), "+f"(d[2]), "+f"(d[3])
        : "r"(a[0]), "r"(a[1]), "r"(a[2]), "r"(a[3]), "r"(b[0]), "r"(b[1]));
}

// ---------------------------------------------------------------------------
// tf32 tensor-core GEMM:  C[M,N] = A[M,K] * B[N,K]^T   (both K-major)
// Block tile 128 x NB x 32, 8 warps (4x2), warp tile 32 x NB/2.
// MODE 0: QKV   A=g_t(8192,768)        B=qkv_w(2304,768)  -> scatter q/k/vt
// MODE 1: QK^T  A=q_z(1024,192)        B=k_z(1024,192)    -> g_attn
// MODE 2: AV    A=attn_z(1024,1024)    B=vt_z(192,1024)   -> g_om (merged)
// MODE 3: PROJ  A=g_om(8192,768)       B=proj_w(768,768)  -> g_proj (+bias)
// ---------------------------------------------------------------------------
template <int MODE>
__global__ __launch_bounds__(256, 1) void tc_gemm(const float* __restrict__ W,
                                                  const float* __restrict__ bias) {
    constexpr int BK  = 32;
    constexpr int NB  = (MODE == 2) ? 96 : 128;
    constexpr int KK  = (MODE == 1) ? 192 : (MODE == 2) ? 1024 : 768;
    constexpr int LD  = (MODE == 1) ? 192 : (MODE == 2) ? 1024 : 768;
    constexpr int T   = KK / BK;
    constexpr int AWORDS = 128 * BK;        // 4096
    constexpr int BWORDS = NB * BK;
    constexpr int WN  = NB / 2;             // 64 or 48
    constexpr int NT  = WN / 8;             // 8 or 6
    constexpr int NBREG = NB / 32;          // B float4 loads per thread

    extern __shared__ float sm[];
    float* As = sm;                         // [2][AWORDS]
    float* Bs = sm + 2 * AWORDS;            // [2][BWORDS]

    const int tid  = threadIdx.x;
    const int lane = tid & 31;
    const int w    = tid >> 5;
    const int wm   = w >> 1;                // 0..3
    const int wn   = w & 1;                 // 0..1
    const int q    = lane >> 2;             // 0..7
    const int lq   = lane & 3;              // 0..3
    const int m0   = blockIdx.y * 128;
    const int n0   = blockIdx.x * NB;
    const int z    = blockIdx.z;

    const float* gA;
    const float* gB;
    if constexpr (MODE == 0) { gA = g_t;                            gB = W; }
    if constexpr (MODE == 1) { gA = g_q + z * (HW * DHd);           gB = g_k + z * (HW * DHd); }
    if constexpr (MODE == 2) { gA = g_attn + (size_t)z * (HW * HW); gB = g_vt + z * (DHd * HW); }
    if constexpr (MODE == 3) { gA = g_om;                           gB = W; }

    const float* aRow = gA + (size_t)m0 * LD;
    const float* bRow = gB + (size_t)n0 * LD;

    float4 pa[4], pb[NBREG];

    auto loadG = [&](int it) {
        const float* aP = aRow + it * BK;
        const float* bP = bRow + it * BK;
#pragma unroll
        for (int i = 0; i < 4; i++) {
            int idx = tid + 256 * i;
            int r = idx >> 3, c = (idx & 7) * 4;
            pa[i] = *reinterpret_cast<const float4*>(aP + (size_t)r * LD + c);
        }
#pragma unroll
        for (int i = 0; i < NBREG; i++) {
            int idx = tid + 256 * i;
            int r = idx >> 3, c = (idx & 7) * 4;
            pb[i] = *reinterpret_cast<const float4*>(bP + (size_t)r * LD + c);
        }
    };
    auto storeS = [&](int buf) {
        uint32_t* A_ = reinterpret_cast<uint32_t*>(As + buf * AWORDS);
        uint32_t* B_ = reinterpret_cast<uint32_t*>(Bs + buf * BWORDS);
#pragma unroll
        for (int i = 0; i < 4; i++) {
            int idx = tid + 256 * i;
            int r = idx >> 3, c = (idx & 7) * 4;
            uint4 v = {f2tf(pa[i].x), f2tf(pa[i].y), f2tf(pa[i].z), f2tf(pa[i].w)};
            *reinterpret_cast<uint4*>(A_ + r * 32 + (c ^ (4 * (r & 7)))) = v;
        }
#pragma unroll
        for (int i = 0; i < NBREG; i++) {
            int idx = tid + 256 * i;
            int r = idx >> 3, c = (idx & 7) * 4;
            uint4 v = {f2tf(pb[i].x), f2tf(pb[i].y), f2tf(pb[i].z), f2tf(pb[i].w)};
            *reinterpret_cast<uint4*>(B_ + r * 32 + (c ^ (4 * (r & 7)))) = v;
        }
    };

    float acc[2][NT][4];
#pragma unroll
    for (int mt = 0; mt < 2; mt++)
#pragma unroll
        for (int nt = 0; nt < NT; nt++)
#pragma unroll
            for (int k = 0; k < 4; k++) acc[mt][nt][k] = 0.f;

    loadG(0);
    storeS(0);
    __syncthreads();

    const int sw = 4 * q;                   // frag-row swizzle (row&7 == q always)

    for (int it = 0; it < T; ++it) {
        if (it + 1 < T) loadG(it + 1);

        const uint32_t* A_ = reinterpret_cast<const uint32_t*>(As + (it & 1) * AWORDS);
        const uint32_t* B_ = reinterpret_cast<const uint32_t*>(Bs + (it & 1) * BWORDS);
#pragma unroll
        for (int ks = 0; ks < 4; ks++) {
            const int k0 = ks * 8;
            const int c0 = (k0 + lq) ^ sw;
            const int c1 = (k0 + 4 + lq) ^ sw;
            uint32_t a[2][4];
#pragma unroll
            for (int mt = 0; mt < 2; mt++) {
                int rb = (wm * 32 + mt * 16 + q) * 32;
                a[mt][0] = A_[rb + c0];
                a[mt][1] = A_[rb + 256 + c0];
                a[mt][2] = A_[rb + c1];
                a[mt][3] = A_[rb + 256 + c1];
            }
            uint32_t b[NT][2];
#pragma unroll
            for (int nt = 0; nt < NT; nt++) {
                int nb = (wn * WN + nt * 8 + q) * 32;
                b[nt][0] = B_[nb + c0];
                b[nt][1] = B_[nb + c1];
            }
#pragma unroll
            for (int mt = 0; mt < 2; mt++)
#pragma unroll
                for (int nt = 0; nt < NT; nt++)
                    mma_tf32(acc[mt][nt], a[mt], b[nt]);
        }

        if (it + 1 < T) {
            __syncthreads();
            storeS((it + 1) & 1);
            __syncthreads();
        }
    }

    // ---------------- epilogue (registers -> global) ----------------
    const int mrb = m0 + wm * 32;
    const int ncb = n0 + wn * WN;
    int s0 = 0;
    if constexpr (MODE == 0) s0 = n0 / 768;          // 0=q, 1=k, 2=v

#pragma unroll
    for (int mt = 0; mt < 2; mt++)
#pragma unroll
        for (int nt = 0; nt < NT; nt++) {
            int r = mrb + mt * 16 + q;
            int c = ncb + nt * 8 + lq * 2;
            float2 v0 = {acc[mt][nt][0], acc[mt][nt][1]};   // (r,   c)
            float2 v1 = {acc[mt][nt][2], acc[mt][nt][3]};   // (r+8, c)
            if constexpr (MODE == 1) {
                float* p = g_attn + (size_t)z * (HW * HW);
                *reinterpret_cast<float2*>(p + (size_t)r * HW + c) = v0;
                *reinterpret_cast<float2*>(p + (size_t)(r + 8) * HW + c) = v1;
            } else if constexpr (MODE == 2) {
                int b = z >> 2, h = z & 3;
                *reinterpret_cast<float2*>(g_om + ((size_t)(b * HW + r)) * DIM + h * DHd + c) = v0;
                *reinterpret_cast<float2*>(g_om + ((size_t)(b * HW + r + 8)) * DIM + h * DHd + c) = v1;
            } else if constexpr (MODE == 3) {
                float2 bb = *reinterpret_cast<const float2*>(bias + c);
                v0.x += bb.x; v0.y += bb.y; v1.x += bb.x; v1.y += bb.y;
                *reinterpret_cast<float2*>(g_proj + (size_t)r * DIM + c) = v0;
                *reinterpret_cast<float2*>(g_proj + (size_t)(r + 8) * DIM + c) = v1;
            } else {  // MODE 0
                int nl = c - s0 * 768;
                int h = nl / 192, dh = nl % 192;
                int b0i = r >> 10, seq0 = r & 1023;
                int b1i = (r + 8) >> 10, seq1 = (r + 8) & 1023;
                if (s0 == 2) {
                    int z0 = b0i * 4 + h, z1 = b1i * 4 + h;
                    g_vt[((size_t)z0 * 192 + dh) * 1024 + seq0]     = v0.x;
                    g_vt[((size_t)z0 * 192 + dh + 1) * 1024 + seq0] = v0.y;
                    g_vt[((size_t)z1 * 192 + dh) * 1024 + seq1]     = v1.x;
                    g_vt[((size_t)z1 * 192 + dh + 1) * 1024 + seq1] = v1.y;
                } else {
                    float* dst = (s0 == 0) ? g_q : g_k;
                    *reinterpret_cast<float2*>(dst + ((size_t)(b0i * 4 + h) * 1024 + seq0) * 192 + dh) = v0;
                    *reinterpret_cast<float2*>(dst + ((size_t)(b1i * 4 + h) * 1024 + seq1) * 192 + dh) = v1;
                }
            }
        }
}

// ---------------------------------------------------------------------------
// Elementwise kernels (unchanged from passing R1 version)
// ---------------------------------------------------------------------------
__global__ void permute_add_pos(const float* __restrict__ x,
                                const float* __restrict__ pos) {
    int i = blockIdx.x * 256 + threadIdx.x;
    if (i >= SEQROWS * DIM) return;
    int cd = i % DIM;
    int t  = i / DIM;
    int hw = t % HW;
    int b  = t / HW;
    int c = cd >> 3, d = cd & 7;
    g_t[i] = x[((b * Cc + c) * Dd + d) * HW + hw] + pos[hw * DIM + cd];
}

__global__ void l2norm_seq() {
    int bh = blockIdx.x & 31;
    float* p = (blockIdx.x < 32 ? g_q : g_k) + bh * (HW * DHd);
    int d = threadIdx.x;
    float ss = 0.f;
#pragma unroll 4
    for (int n = 0; n < HW; n++) {
        float v = p[n * DHd + d];
        ss += v * v;
    }
    float inv = 1.f / fmaxf(sqrtf(ss), 1e-12f);
#pragma unroll 4
    for (int n = 0; n < HW; n++) p[n * DHd + d] *= inv;
}

__global__ void softmax_rows(const float* __restrict__ temp) {
    __shared__ float red[256];
    int row = blockIdx.x;
    int tid = threadIdx.x;
    float* p = g_attn + (size_t)row * HW;
    int h = (row >> 10) & 3;
    float ts = temp[h];

    float v[4];
    float mx = -1e30f;
#pragma unroll
    for (int j = 0; j < 4; j++) {
        v[j] = p[tid + 256 * j] * ts;
        mx = fmaxf(mx, v[j]);
    }
    red[tid] = mx; __syncthreads();
    for (int s = 128; s > 0; s >>= 1) {
        if (tid < s) red[tid] = fmaxf(red[tid], red[tid + s]);
        __syncthreads();
    }
    mx = red[0]; __syncthreads();

    float sum = 0.f;
#pragma unroll
    for (int j = 0; j < 4; j++) {
        v[j] = expf(v[j] - mx);
        sum += v[j];
    }
    red[tid] = sum; __syncthreads();
    for (int s = 128; s > 0; s >>= 1) {
        if (tid < s) red[tid] += red[tid + s];
        __syncthreads();
    }
    float inv = 1.f / red[0];
#pragma unroll
    for (int j = 0; j < 4; j++) p[tid + 256 * j] = v[j] * inv;
}

__global__ void ln_residual(const float* __restrict__ x,
                            const float* __restrict__ gamma,
                            const float* __restrict__ beta) {
    __shared__ float red[256];
    int row = blockIdx.x;
    int tid = threadIdx.x;
    const float* basep = g_proj + (size_t)row * DIM;

    float v[3];
    float s = 0.f;
#pragma unroll
    for (int j = 0; j < 3; j++) {
        v[j] = basep[tid + 256 * j];
        s += v[j];
    }
    red[tid] = s; __syncthreads();
    for (int st = 128; st > 0; st >>= 1) {
        if (tid < st) red[tid] += red[tid + st];
        __syncthreads();
    }
    float mu = red[0] * (1.f / DIM); __syncthreads();

    float s2 = 0.f;
#pragma unroll
    for (int j = 0; j < 3; j++) {
        float d = v[j] - mu;
        s2 += d * d;
    }
    red[tid] = s2; __syncthreads();
    for (int st = 128; st > 0; st >>= 1) {
        if (tid < st) red[tid] += red[tid + st];
        __syncthreads();
    }
    float rstd = rsqrtf(red[0] * (1.f / DIM) + 1e-5f);

    int b = row >> 10, hw = row & 1023;
#pragma unroll
    for (int j = 0; j < 3; j++) {
        int cd = tid + 256 * j;
        float val = (v[j] - mu) * rstd * gamma[cd] + beta[cd];
        int c = cd >> 3, d = cd & 7;
        int idx = ((b * Cc + c) * Dd + d) * HW + hw;
        g_y[idx] = val + x[idx];
    }
}

__global__ __launch_bounds__(1024) void dwconv(const float* __restrict__ dw_w,
                                               const float* __restrict__ dw_b) {
    __shared__ float tile[3][34][34];
    __shared__ float wsh[27];
    int bcd = blockIdx.x;
    int d  = bcd & 7;
    int bc = bcd >> 3;
    int c  = bc % Cc;
    int tid = threadIdx.x;

    if (tid < 27) wsh[tid] = dw_w[c * 27 + tid];

    for (int idx = tid; idx < 3 * 34 * 34; idx += 1024) {
        int pl = idx / 1156;
        int r  = (idx - pl * 1156) / 34;
        int cc = idx - pl * 1156 - r * 34;
        int dd = d - 1 + pl, hh = r - 1, ww = cc - 1;
        float val = 0.f;
        if (dd >= 0 && dd < Dd && hh >= 0 && hh < Hh && ww >= 0 && ww < Ww)
            val = g_y[(bc * Dd + dd) * HW + hh * Ww + ww];
        tile[pl][r][cc] = val;
    }
    __syncthreads();

    int h = tid >> 5, w = tid & 31;
    float s = 0.f;
#pragma unroll
    for (int pl = 0; pl < 3; pl++)
#pragma unroll
        for (int i = 0; i < 3; i++)
#pragma unroll
            for (int j = 0; j < 3; j++)
                s += tile[pl][h + i][w + j] * wsh[pl * 9 + i * 3 + j];
    g_z[bcd * HW + tid] = s + dw_b[c];
}

__global__ __launch_bounds__(128) void pwconv(const float* __restrict__ pw_w,
                                              const float* __restrict__ pw_b,
                                              float* __restrict__ out) {
    __shared__ float wsh[Cc * Cc];
    int b = blockIdx.y;
    int pos = blockIdx.x * 128 + threadIdx.x;
    constexpr int SP = Dd * HW;

    for (int i = threadIdx.x; i < Cc * Cc; i += 128) wsh[i] = pw_w[i];
    __syncthreads();

    float acc[Cc];
#pragma unroll
    for (int co = 0; co < Cc; co++) acc[co] = 0.f;

    const float* zb = g_z + b * Cc * SP + pos;
    for (int ci = 0; ci < Cc; ci++) {
        float zv = zb[ci * SP];
#pragma unroll
        for (int co = 0; co < Cc; co++) acc[co] += zv * wsh[co * Cc + ci];
    }

    const float* yb = g_y + b * Cc * SP + pos;
    float* ob = out + b * Cc * SP + pos;
#pragma unroll
    for (int co = 0; co < Cc; co++)
        ob[co * SP] = yb[co * SP] + acc[co] + pw_b[co];
}

// ---------------------------------------------------------------------------
// Launch
// ---------------------------------------------------------------------------
extern "C" void kernel_launch(void* const* d_in, const int* in_sizes, int n_in,
                              void* d_out, int out_size) {
    const float* x      = (const float*)d_in[0];
    const float* pos    = (const float*)d_in[1];
    const float* qkv_w  = (const float*)d_in[2];
    const float* proj_w = (const float*)d_in[3];
    const float* proj_b = (const float*)d_in[4];
    const float* temp   = (const float*)d_in[5];
    const float* ln_g   = (const float*)d_in[6];
    const float* ln_b   = (const float*)d_in[7];
    const float* dw_w   = (const float*)d_in[8];
    const float* dw_b   = (const float*)d_in[9];
    const float* pw_w   = (const float*)d_in[10];
    const float* pw_b   = (const float*)d_in[11];
    float* out = (float*)d_out;

    constexpr int SMEM128 = 2 * (4096 + 4096) * 4;   // 64 KB
    constexpr int SMEM96  = 2 * (4096 + 3072) * 4;   // 56 KB
    static bool attr_done = false;
    if (!attr_done) {
        cudaFuncSetAttribute(tc_gemm<0>, cudaFuncAttributeMaxDynamicSharedMemorySize, SMEM128);
        cudaFuncSetAttribute(tc_gemm<1>, cudaFuncAttributeMaxDynamicSharedMemorySize, SMEM128);
        cudaFuncSetAttribute(tc_gemm<2>, cudaFuncAttributeMaxDynamicSharedMemorySize, SMEM96);
        cudaFuncSetAttribute(tc_gemm<3>, cudaFuncAttributeMaxDynamicSharedMemorySize, SMEM128);
        attr_done = true;
    }

    permute_add_pos<<<(SEQROWS * DIM + 255) / 256, 256>>>(x, pos);
    tc_gemm<0><<<dim3(18, 64, 1), 256, SMEM128>>>(qkv_w, nullptr);
    l2norm_seq<<<64, 192>>>();
    tc_gemm<1><<<dim3(8, 8, 32), 256, SMEM128>>>(nullptr, nullptr);
    softmax_rows<<<BH * HW, 256>>>(temp);
    tc_gemm<2><<<dim3(2, 8, 32), 256, SMEM96>>>(nullptr, nullptr);
    tc_gemm<3><<<dim3(6, 64, 1), 256, SMEM128>>>(proj_w, proj_b);
    ln_residual<<<SEQROWS, 256>>>(x, ln_g, ln_b);
    dwconv<<<Bn * Cc * Dd, 1024>>>(dw_w, dw_b);
    pwconv<<<dim3(64, Bn, 1), 128>>>(pw_w, pw_b, out);
}

// round 5
// speedup vs baseline: 2.8647x; 1.3693x over previous
#include <cuda_runtime.h>
#include <math.h>
#include <stdint.h>

// ---------------------------------------------------------------------------
// Problem constants
// ---------------------------------------------------------------------------
constexpr int Bn = 8, Cc = 96, Dd = 8, Hh = 32, Ww = 32;
constexpr int HW = Hh * Ww;          // 1024
constexpr int DIM = Cc * Dd;         // 768
constexpr int NH = 4;
constexpr int DHd = DIM / NH;        // 192
constexpr int SEQROWS = Bn * HW;     // 8192
constexpr int BH = Bn * NH;          // 32

// ---------------------------------------------------------------------------
// Scratch (device globals -- no allocations allowed)
// ---------------------------------------------------------------------------
__device__ float g_t[SEQROWS * DIM];
__device__ float g_wq[3 * DIM * DIM];                   // qkv_w, tf32-rounded
__device__ float g_wp[DIM * DIM];                       // proj_w, tf32-rounded
__device__ float g_q[BH * HW * DHd];
__device__ float g_k[BH * HW * DHd];
__device__ float g_vt[BH * DHd * HW];                   // V transposed: [z][dh][seq]
__device__ float g_attn[(size_t)BH * HW * HW];          // 134 MB
__device__ float g_om[SEQROWS * DIM];
__device__ float g_proj[SEQROWS * DIM];
__device__ float g_y[Bn * Cc * Dd * HW];
__device__ float g_z[Bn * Cc * Dd * HW];
__device__ float g_part[2 * BH * 8 * DHd];              // l2norm partials
__device__ float g_inv[2 * BH * DHd];                   // l2norm 1/||.||

// ---------------------------------------------------------------------------
// Helpers (baseline PTX only)
// ---------------------------------------------------------------------------
__device__ __forceinline__ uint32_t f2tf(float x) {
    uint32_t r; asm("cvt.rna.tf32.f32 %0, %1;" : "=r"(r) : "f"(x)); return r;
}
__device__ __forceinline__ float tfr(float x) { return __uint_as_float(f2tf(x)); }
__device__ __forceinline__ void mma_tf32(float* d, const uint32_t* a,
                                         const uint32_t* b) {
    asm volatile(
        "mma.sync.aligned.m16n8k8.row.col.f32.tf32.tf32.f32 "
        "{%0,%1,%2,%3}, {%4,%5,%6,%7}, {%8,%9}, {%0,%1,%2,%3};"
        : "+f"(d[0]), "+f"(d[1]), "+f"(d[2]), "+f"(d[3])
        : "r"(a[0]), "r"(a[1]), "r"(a[2]), "r"(a[3]), "r"(b[0]), "r"(b[1]));
}
__device__ __forceinline__ void cp_async16(uint32_t dst, const void* src) {
    asm volatile("cp.async.cg.shared.global [%0], [%1], 16;"
                 :: "r"(dst), "l"(src) : "memory");
}
__device__ __forceinline__ void cp_commit() {
    asm volatile("cp.async.commit_group;" ::: "memory");
}
template <int N>
__device__ __forceinline__ void cp_wait() {
    asm volatile("cp.async.wait_group %0;" :: "n"(N) : "memory");
}

// ---------------------------------------------------------------------------
// tf32 tensor-core GEMM:  C[M,N] = A[M,K] * B[N,K]^T   (both K-major, both
// already tf32-rounded in global memory).  Block tile 128 x NB x 32,
// 512 threads (16 warps, 4x4), warp tile 32 x NB/4, 3-stage cp.async.
// Weight operands are bound INSIDE device code (device symbols are not
// valid as host-side kernel arguments -- R4 lesson).
// MODE 0: QKV   A=g_t(8192,768)        B=g_wq(2304,768)   -> scatter q/k/vt
// MODE 1: QK^T  A=q_z(1024,192)        B=k_z(1024,192)    -> g_attn
// MODE 2: AV    A=attn_z(1024,1024)    B=vt_z(192,1024)   -> g_om (cvt)
// MODE 3: PROJ  A=g_om(8192,768)       B=g_wp(768,768)    -> g_proj (+bias)
// ---------------------------------------------------------------------------
template <int MODE>
__global__ __launch_bounds__(512, 1) void tc_gemm(const float* __restrict__ bias) {
    constexpr int BK  = 32;
    constexpr int NB  = (MODE == 2) ? 192 : 256;
    constexpr int KK  = (MODE == 1) ? 192 : (MODE == 2) ? 1024 : 768;
    constexpr int LD  = (MODE == 1) ? 192 : (MODE == 2) ? 1024 : 768;
    constexpr int T   = KK / BK;
    constexpr int AW  = 128 * BK;            // 4096 words
    constexpr int BWD = NB * BK;             // 8192 / 6144 words
    constexpr int STG = AW + BWD;            // words per stage
    constexpr int WN  = NB / 4;              // 64 or 48
    constexpr int NT  = WN / 8;              // 8 or 6
    constexpr int BCH = NB * 8 / 512;        // B 16B-chunks per thread (4 or 3)

    extern __shared__ float sm[];
    const uint32_t smBase = (uint32_t)__cvta_generic_to_shared(sm);

    const int tid  = threadIdx.x;
    const int lane = tid & 31;
    const int w    = tid >> 5;               // 0..15
    const int wm   = w & 3;
    const int wn   = w >> 2;                 // 0..3
    const int q    = lane >> 2;              // 0..7
    const int lq   = lane & 3;               // 0..3
    const int m0   = blockIdx.y * 128;
    const int n0   = blockIdx.x * NB;
    const int z    = blockIdx.z;

    const float* gA;
    const float* gB;
    if constexpr (MODE == 0) { gA = g_t;                            gB = g_wq; }
    if constexpr (MODE == 1) { gA = g_q + z * (HW * DHd);           gB = g_k + z * (HW * DHd); }
    if constexpr (MODE == 2) { gA = g_attn + (size_t)z * (HW * HW); gB = g_vt + z * (DHd * HW); }
    if constexpr (MODE == 3) { gA = g_om;                           gB = g_wp; }

    const float* aRow = gA + (size_t)m0 * LD;
    const float* bRow = gB + (size_t)n0 * LD;

    auto loadStage = [&](int it, int s) {
        const float* aP = aRow + it * BK;
        const float* bP = bRow + it * BK;
        uint32_t sA = smBase + (uint32_t)(s * STG) * 4u;
        uint32_t sB = sA + AW * 4u;
#pragma unroll
        for (int i = 0; i < 2; i++) {
            int idx = tid + 512 * i;
            int r = idx >> 3, c4 = idx & 7;
            uint32_t dst = sA + (uint32_t)(r * 32 + ((c4 * 4) ^ (4 * (r & 7)))) * 4u;
            cp_async16(dst, aP + (size_t)r * LD + c4 * 4);
        }
#pragma unroll
        for (int i = 0; i < BCH; i++) {
            int idx = tid + 512 * i;
            int r = idx >> 3, c4 = idx & 7;
            uint32_t dst = sB + (uint32_t)(r * 32 + ((c4 * 4) ^ (4 * (r & 7)))) * 4u;
            cp_async16(dst, bP + (size_t)r * LD + c4 * 4);
        }
    };

    float acc[2][NT][4];
#pragma unroll
    for (int mt = 0; mt < 2; mt++)
#pragma unroll
        for (int nt = 0; nt < NT; nt++)
#pragma unroll
            for (int k = 0; k < 4; k++) acc[mt][nt][k] = 0.f;

#pragma unroll
    for (int s = 0; s < 3; s++) { loadStage(s, s); cp_commit(); }

    const int sw = 4 * q;

    for (int it = 0; it < T; ++it) {
        cp_wait<2>();
        __syncthreads();

        const int st = it % 3;
        const uint32_t* A_ = reinterpret_cast<const uint32_t*>(sm + st * STG);
        const uint32_t* B_ = A_ + AW;
#pragma unroll
        for (int ks = 0; ks < 4; ks++) {
            const int k0 = ks * 8;
            const int c0 = (k0 + lq) ^ sw;
            const int c1 = (k0 + 4 + lq) ^ sw;
            uint32_t a[2][4];
#pragma unroll
            for (int mt = 0; mt < 2; mt++) {
                int rb = (wm * 32 + mt * 16 + q) * 32;
                a[mt][0] = A_[rb + c0];
                a[mt][1] = A_[rb + 256 + c0];
                a[mt][2] = A_[rb + c1];
                a[mt][3] = A_[rb + 256 + c1];
            }
            uint32_t b[NT][2];
#pragma unroll
            for (int nt = 0; nt < NT; nt++) {
                int nb = (wn * WN + nt * 8 + q) * 32;
                b[nt][0] = B_[nb + c0];
                b[nt][1] = B_[nb + c1];
            }
#pragma unroll
            for (int mt = 0; mt < 2; mt++)
#pragma unroll
                for (int nt = 0; nt < NT; nt++)
                    mma_tf32(acc[mt][nt], a[mt], b[nt]);
        }
        __syncthreads();
        if (it + 3 < T) loadStage(it + 3, st);
        cp_commit();
    }

    // ---------------- epilogue (registers -> global) ----------------
    const int mrb = m0 + wm * 32;
    const int ncb = n0 + wn * WN;
    int s0 = 0;
    if constexpr (MODE == 0) s0 = n0 / 768;          // 0=q, 1=k, 2=v

#pragma unroll
    for (int mt = 0; mt < 2; mt++)
#pragma unroll
        for (int nt = 0; nt < NT; nt++) {
            int r = mrb + mt * 16 + q;
            int c = ncb + nt * 8 + lq * 2;
            float2 v0 = {acc[mt][nt][0], acc[mt][nt][1]};   // (r,   c)
            float2 v1 = {acc[mt][nt][2], acc[mt][nt][3]};   // (r+8, c)
            if constexpr (MODE == 1) {
                float* p = g_attn + (size_t)z * (HW * HW);
                *reinterpret_cast<float2*>(p + (size_t)r * HW + c) = v0;
                *reinterpret_cast<float2*>(p + (size_t)(r + 8) * HW + c) = v1;
            } else if constexpr (MODE == 2) {
                int b = z >> 2, h = z & 3;
                v0.x = tfr(v0.x); v0.y = tfr(v0.y);
                v1.x = tfr(v1.x); v1.y = tfr(v1.y);
                *reinterpret_cast<float2*>(g_om + ((size_t)(b * HW + r)) * DIM + h * DHd + c) = v0;
                *reinterpret_cast<float2*>(g_om + ((size_t)(b * HW + r + 8)) * DIM + h * DHd + c) = v1;
            } else if constexpr (MODE == 3) {
                float2 bb = *reinterpret_cast<const float2*>(bias + c);
                v0.x += bb.x; v0.y += bb.y; v1.x += bb.x; v1.y += bb.y;
                *reinterpret_cast<float2*>(g_proj + (size_t)r * DIM + c) = v0;
                *reinterpret_cast<float2*>(g_proj + (size_t)(r + 8) * DIM + c) = v1;
            } else {  // MODE 0
                int nl = c - s0 * 768;
                int h = nl / 192, dh = nl % 192;
                int b0i = r >> 10, seq0 = r & 1023;
                int b1i = (r + 8) >> 10, seq1 = (r + 8) & 1023;
                if (s0 == 2) {
                    int z0 = b0i * 4 + h, z1 = b1i * 4 + h;
                    g_vt[((size_t)z0 * 192 + dh) * 1024 + seq0]     = tfr(v0.x);
                    g_vt[((size_t)z0 * 192 + dh + 1) * 1024 + seq0] = tfr(v0.y);
                    g_vt[((size_t)z1 * 192 + dh) * 1024 + seq1]     = tfr(v1.x);
                    g_vt[((size_t)z1 * 192 + dh + 1) * 1024 + seq1] = tfr(v1.y);
                } else {
                    float* dst = (s0 == 0) ? g_q : g_k;
                    *reinterpret_cast<float2*>(dst + ((size_t)(b0i * 4 + h) * 1024 + seq0) * 192 + dh) = v0;
                    *reinterpret_cast<float2*>(dst + ((size_t)(b1i * 4 + h) * 1024 + seq1) * 192 + dh) = v1;
                }
            }
        }
}

// ---------------------------------------------------------------------------
// Producers / elementwise
// ---------------------------------------------------------------------------
__global__ void permute_add_pos(const float* __restrict__ x,
                                const float* __restrict__ pos) {
    int i = blockIdx.x * 256 + threadIdx.x;
    if (i >= SEQROWS * DIM) return;
    int cd = i % DIM;
    int t  = i / DIM;
    int hw = t % HW;
    int b  = t / HW;
    int c = cd >> 3, d = cd & 7;
    g_t[i] = tfr(x[((b * Cc + c) * Dd + d) * HW + hw] + pos[hw * DIM + cd]);
}

__global__ void cvt_weights(const float* __restrict__ qkv_w,
                            const float* __restrict__ proj_w) {
    int i = blockIdx.x * 256 + threadIdx.x;
    if (i < 3 * DIM * DIM) g_wq[i] = tfr(qkv_w[i]);
    if (i < DIM * DIM)     g_wp[i] = tfr(proj_w[i]);
}

// l2norm over seq axis: partial sums -> inv -> scale(+tf32 round)
__global__ void l2_part() {
    int chunk = blockIdx.x, z = blockIdx.y, which = blockIdx.z;
    const float* p = (which ? g_k : g_q) + ((size_t)z * HW + chunk * 128) * DHd;
    int col = threadIdx.x;
    float ss = 0.f;
#pragma unroll 4
    for (int r = 0; r < 128; r++) {
        float v = p[(size_t)r * DHd + col];
        ss += v * v;
    }
    g_part[(((size_t)which * BH + z) * 8 + chunk) * DHd + col] = ss;
}

__global__ void l2_inv() {
    int which = blockIdx.x >> 5, z = blockIdx.x & 31;
    int col = threadIdx.x;
    float ss = 0.f;
#pragma unroll
    for (int c = 0; c < 8; c++)
        ss += g_part[(((size_t)which * BH + z) * 8 + c) * DHd + col];
    g_inv[((size_t)which * BH + z) * DHd + col] = 1.f / fmaxf(sqrtf(ss), 1e-12f);
}

__global__ void l2_scale() {
    int which = blockIdx.z, z = blockIdx.y;
    int i = blockIdx.x * 256 + threadIdx.x;           // 0..49151 (float4 units)
    int seq = i / 48, c4 = i % 48;
    float* p = (which ? g_k : g_q) + ((size_t)z * HW + seq) * DHd + c4 * 4;
    float4 v  = *reinterpret_cast<float4*>(p);
    float4 iv = *reinterpret_cast<const float4*>(g_inv + ((size_t)which * BH + z) * DHd + c4 * 4);
    v.x = tfr(v.x * iv.x); v.y = tfr(v.y * iv.y);
    v.z = tfr(v.z * iv.z); v.w = tfr(v.w * iv.w);
    *reinterpret_cast<float4*>(p) = v;
}

__global__ void softmax_rows(const float* __restrict__ temp) {
    __shared__ float red[256];
    int row = blockIdx.x;
    int tid = threadIdx.x;
    float* p = g_attn + (size_t)row * HW;
    int h = (row >> 10) & 3;
    float ts = temp[h];

    float v[4];
    float mx = -1e30f;
#pragma unroll
    for (int j = 0; j < 4; j++) {
        v[j] = p[tid + 256 * j] * ts;
        mx = fmaxf(mx, v[j]);
    }
    red[tid] = mx; __syncthreads();
    for (int s = 128; s > 0; s >>= 1) {
        if (tid < s) red[tid] = fmaxf(red[tid], red[tid + s]);
        __syncthreads();
    }
    mx = red[0]; __syncthreads();

    float sum = 0.f;
#pragma unroll
    for (int j = 0; j < 4; j++) {
        v[j] = expf(v[j] - mx);
        sum += v[j];
    }
    red[tid] = sum; __syncthreads();
    for (int s = 128; s > 0; s >>= 1) {
        if (tid < s) red[tid] += red[tid + s];
        __syncthreads();
    }
    float inv = 1.f / red[0];
#pragma unroll
    for (int j = 0; j < 4; j++) p[tid + 256 * j] = tfr(v[j] * inv);
}

__global__ void ln_residual(const float* __restrict__ x,
                            const float* __restrict__ gamma,
                            const float* __restrict__ beta) {
    __shared__ float red[256];
    int row = blockIdx.x;
    int tid = threadIdx.x;
    const float* basep = g_proj + (size_t)row * DIM;

    float v[3];
    float s = 0.f;
#pragma unroll
    for (int j = 0; j < 3; j++) {
        v[j] = basep[tid + 256 * j];
        s += v[j];
    }
    red[tid] = s; __syncthreads();
    for (int st = 128; st > 0; st >>= 1) {
        if (tid < st) red[tid] += red[tid + st];
        __syncthreads();
    }
    float mu = red[0] * (1.f / DIM); __syncthreads();

    float s2 = 0.f;
#pragma unroll
    for (int j = 0; j < 3; j++) {
        float d = v[j] - mu;
        s2 += d * d;
    }
    red[tid] = s2; __syncthreads();
    for (int st = 128; st > 0; st >>= 1) {
        if (tid < st) red[tid] += red[tid + st];
        __syncthreads();
    }
    float rstd = rsqrtf(red[0] * (1.f / DIM) + 1e-5f);

    int b = row >> 10, hw = row & 1023;
#pragma unroll
    for (int j = 0; j < 3; j++) {
        int cd = tid + 256 * j;
        float val = (v[j] - mu) * rstd * gamma[cd] + beta[cd];
        int c = cd >> 3, d = cd & 7;
        int idx = ((b * Cc + c) * Dd + d) * HW + hw;
        g_y[idx] = val + x[idx];
    }
}

__global__ __launch_bounds__(1024) void dwconv(const float* __restrict__ dw_w,
                                               const float* __restrict__ dw_b) {
    __shared__ float tile[3][34][34];
    __shared__ float wsh[27];
    int bcd = blockIdx.x;
    int d  = bcd & 7;
    int bc = bcd >> 3;
    int c  = bc % Cc;
    int tid = threadIdx.x;

    if (tid < 27) wsh[tid] = dw_w[c * 27 + tid];

    for (int idx = tid; idx < 3 * 34 * 34; idx += 1024) {
        int pl = idx / 1156;
        int r  = (idx - pl * 1156) / 34;
        int cc = idx - pl * 1156 - r * 34;
        int dd = d - 1 + pl, hh = r - 1, ww = cc - 1;
        float val = 0.f;
        if (dd >= 0 && dd < Dd && hh >= 0 && hh < Hh && ww >= 0 && ww < Ww)
            val = g_y[(bc * Dd + dd) * HW + hh * Ww + ww];
        tile[pl][r][cc] = val;
    }
    __syncthreads();

    int h = tid >> 5, w = tid & 31;
    float s = 0.f;
#pragma unroll
    for (int pl = 0; pl < 3; pl++)
#pragma unroll
        for (int i = 0; i < 3; i++)
#pragma unroll
            for (int j = 0; j < 3; j++)
                s += tile[pl][h + i][w + j] * wsh[pl * 9 + i * 3 + j];
    g_z[bcd * HW + tid] = s + dw_b[c];
}

__global__ __launch_bounds__(128) void pwconv(const float* __restrict__ pw_w,
                                              const float* __restrict__ pw_b,
                                              float* __restrict__ out) {
    __shared__ float wsh[Cc * Cc];
    int b = blockIdx.y;
    int pos = blockIdx.x * 128 + threadIdx.x;
    constexpr int SP = Dd * HW;

    for (int i = threadIdx.x; i < Cc * Cc; i += 128) wsh[i] = pw_w[i];
    __syncthreads();

    float acc[Cc];
#pragma unroll
    for (int co = 0; co < Cc; co++) acc[co] = 0.f;

    const float* zb = g_z + b * Cc * SP + pos;
    for (int ci = 0; ci < Cc; ci++) {
        float zv = zb[ci * SP];
#pragma unroll
        for (int co = 0; co < Cc; co++) acc[co] += zv * wsh[co * Cc + ci];
    }

    const float* yb = g_y + b * Cc * SP + pos;
    float* ob = out + b * Cc * SP + pos;
#pragma unroll
    for (int co = 0; co < Cc; co++)
        ob[co * SP] = yb[co * SP] + acc[co] + pw_b[co];
}

// ---------------------------------------------------------------------------
// Launch
// ---------------------------------------------------------------------------
extern "C" void kernel_launch(void* const* d_in, const int* in_sizes, int n_in,
                              void* d_out, int out_size) {
    const float* x      = (const float*)d_in[0];
    const float* pos    = (const float*)d_in[1];
    const float* qkv_w  = (const float*)d_in[2];
    const float* proj_w = (const float*)d_in[3];
    const float* proj_b = (const float*)d_in[4];
    const float* temp   = (const float*)d_in[5];
    const float* ln_g   = (const float*)d_in[6];
    const float* ln_b   = (const float*)d_in[7];
    const float* dw_w   = (const float*)d_in[8];
    const float* dw_b   = (const float*)d_in[9];
    const float* pw_w   = (const float*)d_in[10];
    const float* pw_b   = (const float*)d_in[11];
    float* out = (float*)d_out;

    constexpr int SMEM256 = 3 * (4096 + 8192) * 4;   // 144 KB
    constexpr int SMEM192 = 3 * (4096 + 6144) * 4;   // 120 KB
    cudaFuncSetAttribute(tc_gemm<0>, cudaFuncAttributeMaxDynamicSharedMemorySize, SMEM256);
    cudaFuncSetAttribute(tc_gemm<1>, cudaFuncAttributeMaxDynamicSharedMemorySize, SMEM256);
    cudaFuncSetAttribute(tc_gemm<2>, cudaFuncAttributeMaxDynamicSharedMemorySize, SMEM192);
    cudaFuncSetAttribute(tc_gemm<3>, cudaFuncAttributeMaxDynamicSharedMemorySize, SMEM256);

    permute_add_pos<<<(SEQROWS * DIM + 255) / 256, 256>>>(x, pos);
    cvt_weights<<<(3 * DIM * DIM + 255) / 256, 256>>>(qkv_w, proj_w);
    tc_gemm<0><<<dim3(9, 64, 1), 512, SMEM256>>>(nullptr);
    l2_part<<<dim3(8, 32, 2), 192>>>();
    l2_inv<<<64, 192>>>();
    l2_scale<<<dim3(192, 32, 2), 256>>>();
    tc_gemm<1><<<dim3(4, 8, 32), 512, SMEM256>>>(nullptr);
    softmax_rows<<<BH * HW, 256>>>(temp);
    tc_gemm<2><<<dim3(1, 8, 32), 512, SMEM192>>>(nullptr);
    tc_gemm<3><<<dim3(3, 64, 1), 512, SMEM256>>>(proj_b);
    ln_residual<<<SEQROWS, 256>>>(x, ln_g, ln_b);
    dwconv<<<Bn * Cc * Dd, 1024>>>(dw_w, dw_b);
    pwconv<<<dim3(64, Bn, 1), 128>>>(pw_w, pw_b, out);
}

// round 6
// speedup vs baseline: 3.2485x; 1.1339x over previous
#include <cuda_runtime.h>
#include <math.h>
#include <stdint.h>

// ---------------------------------------------------------------------------
// Problem constants
// ---------------------------------------------------------------------------
constexpr int Bn = 8, Cc = 96, Dd = 8, Hh = 32, Ww = 32;
constexpr int HW = Hh * Ww;          // 1024
constexpr int DIM = Cc * Dd;         // 768
constexpr int NH = 4;
constexpr int DHd = DIM / NH;        // 192
constexpr int SEQROWS = Bn * HW;     // 8192
constexpr int BH = Bn * NH;          // 32

// ---------------------------------------------------------------------------
// Scratch (device globals -- no allocations allowed)
// ---------------------------------------------------------------------------
__device__ float g_t[SEQROWS * DIM];
__device__ float g_wq[3 * DIM * DIM];                   // qkv_w, tf32-rounded
__device__ float g_wp[DIM * DIM];                       // proj_w, tf32-rounded
__device__ float g_q[BH * HW * DHd];
__device__ float g_k[BH * HW * DHd];
__device__ float g_vt[BH * DHd * HW];                   // V transposed: [z][dh][seq]
__device__ float g_om[SEQROWS * DIM];
__device__ float g_proj[SEQROWS * DIM];
__device__ float g_y[Bn * Cc * Dd * HW];
__device__ float g_z[Bn * Cc * Dd * HW];
__device__ float g_part[2 * BH * 8 * DHd];              // l2norm partials
__device__ float g_inv[2 * BH * DHd];                   // l2norm 1/||.||
__device__ float g_mu[SEQROWS];
__device__ float g_rs[SEQROWS];

// ---------------------------------------------------------------------------
// Helpers (baseline PTX only)
// ---------------------------------------------------------------------------
__device__ __forceinline__ uint32_t f2tf(float x) {
    uint32_t r; asm("cvt.rna.tf32.f32 %0, %1;" : "=r"(r) : "f"(x)); return r;
}
__device__ __forceinline__ float tfr(float x) { return __uint_as_float(f2tf(x)); }
__device__ __forceinline__ void mma_tf32(float* d, const uint32_t* a,
                                         const uint32_t* b) {
    asm volatile(
        "mma.sync.aligned.m16n8k8.row.col.f32.tf32.tf32.f32 "
        "{%0,%1,%2,%3}, {%4,%5,%6,%7}, {%8,%9}, {%0,%1,%2,%3};"
        : "+f"(d[0]), "+f"(d[1]), "+f"(d[2]), "+f"(d[3])
        : "r"(a[0]), "r"(a[1]), "r"(a[2]), "r"(a[3]), "r"(b[0]), "r"(b[1]));
}
__device__ __forceinline__ void cp_async16(uint32_t dst, const void* src) {
    asm volatile("cp.async.cg.shared.global [%0], [%1], 16;"
                 :: "r"(dst), "l"(src) : "memory");
}
__device__ __forceinline__ void cp_commit() {
    asm volatile("cp.async.commit_group;" ::: "memory");
}
template <int N>
__device__ __forceinline__ void cp_wait() {
    asm volatile("cp.async.wait_group %0;" :: "n"(N) : "memory");
}

// ---------------------------------------------------------------------------
// tf32 GEMM for QKV / PROJ:  C[M,N] = A[M,K] * B[N,K]^T, K=768.
// Block tile 128 x 256 x 32, 512 threads, warp tile 32x64, 3-stage cp.async.
// MODE 0: QKV   A=g_t(8192,768)  B=g_wq(2304,768)  -> scatter q/k/vt
// MODE 3: PROJ  A=g_om(8192,768) B=g_wp(768,768)   -> g_proj (+bias)
// ---------------------------------------------------------------------------
template <int MODE>
__global__ __launch_bounds__(512, 1) void tc_gemm(const float* __restrict__ bias) {
    constexpr int BK  = 32;
    constexpr int NB  = 256;
    constexpr int KK  = 768;
    constexpr int LD  = 768;
    constexpr int T   = KK / BK;
    constexpr int AW  = 128 * BK;            // 4096 words
    constexpr int BWD = NB * BK;             // 8192 words
    constexpr int STG = AW + BWD;
    constexpr int WN  = 64;
    constexpr int NT  = 8;

    extern __shared__ float sm[];
    const uint32_t smBase = (uint32_t)__cvta_generic_to_shared(sm);

    const int tid  = threadIdx.x;
    const int lane = tid & 31;
    const int w    = tid >> 5;
    const int wm   = w & 3;
    const int wn   = w >> 2;
    const int q    = lane >> 2;
    const int lq   = lane & 3;
    const int m0   = blockIdx.y * 128;
    const int n0   = blockIdx.x * NB;

    const float* gA = (MODE == 0) ? g_t  : g_om;
    const float* gB = (MODE == 0) ? g_wq : g_wp;

    const float* aRow = gA + (size_t)m0 * LD;
    const float* bRow = gB + (size_t)n0 * LD;

    auto loadStage = [&](int it, int s) {
        const float* aP = aRow + it * BK;
        const float* bP = bRow + it * BK;
        uint32_t sA = smBase + (uint32_t)(s * STG) * 4u;
        uint32_t sB = sA + AW * 4u;
#pragma unroll
        for (int i = 0; i < 2; i++) {
            int idx = tid + 512 * i;
            int r = idx >> 3, c4 = idx & 7;
            uint32_t dst = sA + (uint32_t)(r * 32 + ((c4 * 4) ^ (4 * (r & 7)))) * 4u;
            cp_async16(dst, aP + (size_t)r * LD + c4 * 4);
        }
#pragma unroll
        for (int i = 0; i < 4; i++) {
            int idx = tid + 512 * i;
            int r = idx >> 3, c4 = idx & 7;
            uint32_t dst = sB + (uint32_t)(r * 32 + ((c4 * 4) ^ (4 * (r & 7)))) * 4u;
            cp_async16(dst, bP + (size_t)r * LD + c4 * 4);
        }
    };

    float acc[2][NT][4];
#pragma unroll
    for (int mt = 0; mt < 2; mt++)
#pragma unroll
        for (int nt = 0; nt < NT; nt++)
#pragma unroll
            for (int k = 0; k < 4; k++) acc[mt][nt][k] = 0.f;

#pragma unroll
    for (int s = 0; s < 3; s++) { loadStage(s, s); cp_commit(); }

    const int sw = 4 * q;

    for (int it = 0; it < T; ++it) {
        cp_wait<2>();
        __syncthreads();

        const int st = it % 3;
        const uint32_t* A_ = reinterpret_cast<const uint32_t*>(sm + st * STG);
        const uint32_t* B_ = A_ + AW;
#pragma unroll
        for (int ks = 0; ks < 4; ks++) {
            const int k0 = ks * 8;
            const int c0 = (k0 + lq) ^ sw;
            const int c1 = (k0 + 4 + lq) ^ sw;
            uint32_t a[2][4];
#pragma unroll
            for (int mt = 0; mt < 2; mt++) {
                int rb = (wm * 32 + mt * 16 + q) * 32;
                a[mt][0] = A_[rb + c0];
                a[mt][1] = A_[rb + 256 + c0];
                a[mt][2] = A_[rb + c1];
                a[mt][3] = A_[rb + 256 + c1];
            }
            uint32_t b[NT][2];
#pragma unroll
            for (int nt = 0; nt < NT; nt++) {
                int nb = (wn * WN + nt * 8 + q) * 32;
                b[nt][0] = B_[nb + c0];
                b[nt][1] = B_[nb + c1];
            }
#pragma unroll
            for (int mt = 0; mt < 2; mt++)
#pragma unroll
                for (int nt = 0; nt < NT; nt++)
                    mma_tf32(acc[mt][nt], a[mt], b[nt]);
        }
        __syncthreads();
        if (it + 3 < T) loadStage(it + 3, st);
        cp_commit();
    }

    // epilogue
    const int mrb = m0 + wm * 32;
    const int ncb = n0 + wn * WN;
    int s0 = 0;
    if constexpr (MODE == 0) s0 = n0 / 768;

#pragma unroll
    for (int mt = 0; mt < 2; mt++)
#pragma unroll
        for (int nt = 0; nt < NT; nt++) {
            int r = mrb + mt * 16 + q;
            int c = ncb + nt * 8 + lq * 2;
            float2 v0 = {acc[mt][nt][0], acc[mt][nt][1]};
            float2 v1 = {acc[mt][nt][2], acc[mt][nt][3]};
            if constexpr (MODE == 3) {
                float2 bb = *reinterpret_cast<const float2*>(bias + c);
                v0.x += bb.x; v0.y += bb.y; v1.x += bb.x; v1.y += bb.y;
                *reinterpret_cast<float2*>(g_proj + (size_t)r * DIM + c) = v0;
                *reinterpret_cast<float2*>(g_proj + (size_t)(r + 8) * DIM + c) = v1;
            } else {
                int nl = c - s0 * 768;
                int h = nl / 192, dh = nl % 192;
                int b0i = r >> 10, seq0 = r & 1023;
                int b1i = (r + 8) >> 10, seq1 = (r + 8) & 1023;
                if (s0 == 2) {
                    int z0 = b0i * 4 + h, z1 = b1i * 4 + h;
                    g_vt[((size_t)z0 * 192 + dh) * 1024 + seq0]     = tfr(v0.x);
                    g_vt[((size_t)z0 * 192 + dh + 1) * 1024 + seq0] = tfr(v0.y);
                    g_vt[((size_t)z1 * 192 + dh) * 1024 + seq1]     = tfr(v1.x);
                    g_vt[((size_t)z1 * 192 + dh + 1) * 1024 + seq1] = tfr(v1.y);
                } else {
                    float* dst = (s0 == 0) ? g_q : g_k;
                    *reinterpret_cast<float2*>(dst + ((size_t)(b0i * 4 + h) * 1024 + seq0) * 192 + dh) = v0;
                    *reinterpret_cast<float2*>(dst + ((size_t)(b1i * 4 + h) * 1024 + seq1) * 192 + dh) = v1;
                }
            }
        }
}

// ---------------------------------------------------------------------------
// Flash attention: per CTA 64 query rows x one (b,h). 256 threads, 8 warps
// (wm 2 x wn 4). Phase 1: S = Q K^T (warp tile 32x32); online softmax;
// P -> smem (tf32); Phase 2: O += P V (warp tile 32x48). cp.async chain with
// 3 rotating KV buffers, prefetch depth 2, unconditional commits.
// smem words: Q 6*2048 | KV 3*6144 | P 4*2048 | red 256  = 39168 (153 KB)
// ---------------------------------------------------------------------------
constexpr int FS_Q   = 0;
constexpr int FS_KV  = 12288;
constexpr int FS_P   = 30720;
constexpr int FS_RED = 38912;
constexpr int FS_TOT = 39168;

__global__ __launch_bounds__(256, 1) void flash_attn(const float* __restrict__ temp) {
    extern __shared__ float sm[];
    const uint32_t smBase = (uint32_t)__cvta_generic_to_shared(sm);

    const int tid  = threadIdx.x;
    const int lane = tid & 31;
    const int w    = tid >> 5;       // 0..7
    const int wm   = w & 1;
    const int wn   = w >> 1;         // 0..3
    const int q    = lane >> 2;
    const int lq   = lane & 3;
    const int z    = blockIdx.y;
    const int m0   = blockIdx.x * 64;

    const float* Qz = g_q  + (size_t)z * HW * DHd;
    const float* Kz = g_k  + (size_t)z * HW * DHd;
    const float* Vz = g_vt + (size_t)z * DHd * HW;
    const float ts = temp[z & 3];

    // Q load: 6 panels [64][32] swizzled
#pragma unroll
    for (int i = 0; i < 12; i++) {
        int idx = tid + 256 * i;
        int c4 = idx & 7, r = (idx >> 3) & 63, p = idx >> 9;
        uint32_t dst = smBase + (uint32_t)(FS_Q + p * 2048 + r * 32 +
                                           ((c4 * 4) ^ (4 * (r & 7)))) * 4u;
        cp_async16(dst, Qz + (size_t)(m0 + r) * 192 + p * 32 + c4 * 4);
    }
    cp_commit();

    auto issuePanel = [&](int g) {
        int t = g / 10, i = g % 10, buf = g % 3;
        uint32_t base = smBase + (uint32_t)(FS_KV + buf * 6144) * 4u;
        if (i < 6) {               // K panel: 128 rows x 32 dh
#pragma unroll
            for (int j = 0; j < 4; j++) {
                int idx = tid + 256 * j;
                int c4 = idx & 7, r = idx >> 3;
                cp_async16(base + (uint32_t)(r * 32 + ((c4 * 4) ^ (4 * (r & 7)))) * 4u,
                           Kz + (size_t)(t * 128 + r) * 192 + i * 32 + c4 * 4);
            }
        } else {                   // V panel: 192 dh rows x 32 keys
            int pv = i - 6;
#pragma unroll
            for (int j = 0; j < 6; j++) {
                int idx = tid + 256 * j;
                int c4 = idx & 7, r = idx >> 3;
                cp_async16(base + (uint32_t)(r * 32 + ((c4 * 4) ^ (4 * (r & 7)))) * 4u,
                           Vz + (size_t)r * 1024 + t * 128 + pv * 32 + c4 * 4);
            }
        }
    };
    issuePanel(0); cp_commit();
    issuePanel(1); cp_commit();

    constexpr float L2E = 1.4426950408889634f;
    float m_run[2][2] = {{-1e30f, -1e30f}, {-1e30f, -1e30f}};
    float l_run[2][2] = {{0.f, 0.f}, {0.f, 0.f}};
    float acc_o[2][6][4];
#pragma unroll
    for (int mt = 0; mt < 2; mt++)
#pragma unroll
        for (int nt = 0; nt < 6; nt++)
#pragma unroll
            for (int k = 0; k < 4; k++) acc_o[mt][nt][k] = 0.f;

    const int sw = 4 * q;
    float* sRed = sm + FS_RED;

    for (int t = 0; t < 8; t++) {
        float acc_s[2][4][4];
#pragma unroll
        for (int mt = 0; mt < 2; mt++)
#pragma unroll
            for (int nt = 0; nt < 4; nt++)
#pragma unroll
                for (int k = 0; k < 4; k++) acc_s[mt][nt][k] = 0.f;

        // ---------- phase 1: S = Q K^T ----------
        for (int p = 0; p < 6; p++) {
            int g = t * 10 + p;
            cp_wait<1>();
            __syncthreads();
            if (g + 2 < 80) issuePanel(g + 2);
            cp_commit();
            const uint32_t* Ap = reinterpret_cast<const uint32_t*>(sm + FS_Q + p * 2048);
            const uint32_t* Bp = reinterpret_cast<const uint32_t*>(sm + FS_KV + (g % 3) * 6144);
#pragma unroll
            for (int ks = 0; ks < 4; ks++) {
                const int c0 = (ks * 8 + lq) ^ sw;
                const int c1 = (ks * 8 + 4 + lq) ^ sw;
                uint32_t a[2][4];
#pragma unroll
                for (int mt = 0; mt < 2; mt++) {
                    int rb = (wm * 32 + mt * 16 + q) * 32;
                    a[mt][0] = Ap[rb + c0];
                    a[mt][1] = Ap[rb + 256 + c0];
                    a[mt][2] = Ap[rb + c1];
                    a[mt][3] = Ap[rb + 256 + c1];
                }
#pragma unroll
                for (int nt = 0; nt < 4; nt++) {
                    uint32_t b[2];
                    int nb = (wn * 32 + nt * 8 + q) * 32;
                    b[0] = Bp[nb + c0];
                    b[1] = Bp[nb + c1];
#pragma unroll
                    for (int mt = 0; mt < 2; mt++)
                        mma_tf32(acc_s[mt][nt], a[mt], b);
                }
            }
        }

        // ---------- online softmax ----------
        float tmax[2][2], corr[2][2], rsum[2][2];
        {
            float rmax[2][2] = {{-1e30f, -1e30f}, {-1e30f, -1e30f}};
#pragma unroll
            for (int mt = 0; mt < 2; mt++)
#pragma unroll
                for (int nt = 0; nt < 4; nt++)
#pragma unroll
                    for (int j = 0; j < 4; j++) {
                        float v = acc_s[mt][nt][j] * ts;
                        acc_s[mt][nt][j] = v;
                        rmax[mt][j >> 1] = fmaxf(rmax[mt][j >> 1], v);
                    }
#pragma unroll
            for (int mt = 0; mt < 2; mt++)
#pragma unroll
                for (int h2 = 0; h2 < 2; h2++) {
                    float v = rmax[mt][h2];
                    v = fmaxf(v, __shfl_xor_sync(0xFFFFFFFF, v, 1));
                    v = fmaxf(v, __shfl_xor_sync(0xFFFFFFFF, v, 2));
                    rmax[mt][h2] = v;
                }
            if (lq == 0) {
#pragma unroll
                for (int mt = 0; mt < 2; mt++)
#pragma unroll
                    for (int h2 = 0; h2 < 2; h2++)
                        sRed[wn * 64 + wm * 32 + mt * 16 + q + h2 * 8] = rmax[mt][h2];
            }
            __syncthreads();
#pragma unroll
            for (int mt = 0; mt < 2; mt++)
#pragma unroll
                for (int h2 = 0; h2 < 2; h2++) {
                    int rr = wm * 32 + mt * 16 + q + h2 * 8;
                    tmax[mt][h2] = fmaxf(fmaxf(sRed[rr], sRed[64 + rr]),
                                         fmaxf(sRed[128 + rr], sRed[192 + rr]));
                }
        }
#pragma unroll
        for (int mt = 0; mt < 2; mt++)
#pragma unroll
            for (int h2 = 0; h2 < 2; h2++) {
                float nm = fmaxf(m_run[mt][h2], tmax[mt][h2]);
                corr[mt][h2] = exp2f((m_run[mt][h2] - nm) * L2E);
                m_run[mt][h2] = nm;
                rsum[mt][h2] = 0.f;
            }
#pragma unroll
        for (int mt = 0; mt < 2; mt++)
#pragma unroll
            for (int nt = 0; nt < 4; nt++)
#pragma unroll
                for (int j = 0; j < 4; j++) {
                    float pv = exp2f((acc_s[mt][nt][j] - m_run[mt][j >> 1]) * L2E);
                    acc_s[mt][nt][j] = pv;
                    rsum[mt][j >> 1] += pv;
                }
#pragma unroll
        for (int mt = 0; mt < 2; mt++)
#pragma unroll
            for (int h2 = 0; h2 < 2; h2++) {
                float v = rsum[mt][h2];
                v += __shfl_xor_sync(0xFFFFFFFF, v, 1);
                v += __shfl_xor_sync(0xFFFFFFFF, v, 2);
                rsum[mt][h2] = v;
            }
        __syncthreads();                       // sRed reuse (max -> sum)
        if (lq == 0) {
#pragma unroll
            for (int mt = 0; mt < 2; mt++)
#pragma unroll
                for (int h2 = 0; h2 < 2; h2++)
                    sRed[wn * 64 + wm * 32 + mt * 16 + q + h2 * 8] = rsum[mt][h2];
        }
        __syncthreads();
#pragma unroll
        for (int mt = 0; mt < 2; mt++)
#pragma unroll
            for (int h2 = 0; h2 < 2; h2++) {
                int rr = wm * 32 + mt * 16 + q + h2 * 8;
                float tsum = sRed[rr] + sRed[64 + rr] + sRed[128 + rr] + sRed[192 + rr];
                l_run[mt][h2] = l_run[mt][h2] * corr[mt][h2] + tsum;
            }
        // rescale O
#pragma unroll
        for (int mt = 0; mt < 2; mt++)
#pragma unroll
            for (int nt = 0; nt < 6; nt++) {
                acc_o[mt][nt][0] *= corr[mt][0];
                acc_o[mt][nt][1] *= corr[mt][0];
                acc_o[mt][nt][2] *= corr[mt][1];
                acc_o[mt][nt][3] *= corr[mt][1];
            }
        // store P (tf32) to panel wn
#pragma unroll
        for (int mt = 0; mt < 2; mt++)
#pragma unroll
            for (int nt = 0; nt < 4; nt++) {
                int r0 = wm * 32 + mt * 16 + q;
                int c  = nt * 8 + 2 * lq;
                float2 p0 = {__uint_as_float(f2tf(acc_s[mt][nt][0])),
                             __uint_as_float(f2tf(acc_s[mt][nt][1]))};
                float2 p1 = {__uint_as_float(f2tf(acc_s[mt][nt][2])),
                             __uint_as_float(f2tf(acc_s[mt][nt][3]))};
                *reinterpret_cast<float2*>(sm + FS_P + wn * 2048 + r0 * 32 + (c ^ sw)) = p0;
                *reinterpret_cast<float2*>(sm + FS_P + wn * 2048 + (r0 + 8) * 32 + (c ^ sw)) = p1;
            }
        __syncthreads();

        // ---------- phase 2: O += P V ----------
        for (int pv = 0; pv < 4; pv++) {
            int g = t * 10 + 6 + pv;
            cp_wait<1>();
            __syncthreads();
            if (g + 2 < 80) issuePanel(g + 2);
            cp_commit();
            const uint32_t* Ap = reinterpret_cast<const uint32_t*>(sm + FS_P + pv * 2048);
            const uint32_t* Bp = reinterpret_cast<const uint32_t*>(sm + FS_KV + (g % 3) * 6144);
#pragma unroll
            for (int ks = 0; ks < 4; ks++) {
                const int c0 = (ks * 8 + lq) ^ sw;
                const int c1 = (ks * 8 + 4 + lq) ^ sw;
                uint32_t a[2][4];
#pragma unroll
                for (int mt = 0; mt < 2; mt++) {
                    int rb = (wm * 32 + mt * 16 + q) * 32;
                    a[mt][0] = Ap[rb + c0];
                    a[mt][1] = Ap[rb + 256 + c0];
                    a[mt][2] = Ap[rb + c1];
                    a[mt][3] = Ap[rb + 256 + c1];
                }
#pragma unroll
                for (int nt = 0; nt < 6; nt++) {
                    uint32_t b[2];
                    int nb = (wn * 48 + nt * 8 + q) * 32;
                    b[0] = Bp[nb + c0];
                    b[1] = Bp[nb + c1];
#pragma unroll
                    for (int mt = 0; mt < 2; mt++)
                        mma_tf32(acc_o[mt][nt], a[mt], b);
                }
            }
        }
    }

    // ---------- epilogue: O /= l, merged-head store ----------
    int b = z >> 2, h = z & 3;
    float inv[2][2];
#pragma unroll
    for (int mt = 0; mt < 2; mt++)
#pragma unroll
        for (int h2 = 0; h2 < 2; h2++) inv[mt][h2] = 1.f / l_run[mt][h2];
#pragma unroll
    for (int mt = 0; mt < 2; mt++)
#pragma unroll
        for (int nt = 0; nt < 6; nt++) {
            int rl = wm * 32 + mt * 16 + q;
            int col = wn * 48 + nt * 8 + 2 * lq;
            float2 v0 = {tfr(acc_o[mt][nt][0] * inv[mt][0]),
                         tfr(acc_o[mt][nt][1] * inv[mt][0])};
            float2 v1 = {tfr(acc_o[mt][nt][2] * inv[mt][1]),
                         tfr(acc_o[mt][nt][3] * inv[mt][1])};
            *reinterpret_cast<float2*>(
                g_om + ((size_t)(b * HW + m0 + rl)) * DIM + h * DHd + col) = v0;
            *reinterpret_cast<float2*>(
                g_om + ((size_t)(b * HW + m0 + rl + 8)) * DIM + h * DHd + col) = v1;
        }
}

// ---------------------------------------------------------------------------
// Producers / elementwise
// ---------------------------------------------------------------------------
// permute b c d h w -> b (hw) (cd), +pos, tf32-round; smem tile transpose
__global__ void permute_t(const float* __restrict__ x,
                          const float* __restrict__ pos) {
    __shared__ float tile[32][33];
    int bz = blockIdx.z, hw0 = blockIdx.y * 32, cd0 = blockIdx.x * 32;
    int tx = threadIdx.x, ty = threadIdx.y;
#pragma unroll
    for (int k = 0; k < 4; k++) {
        int cd = cd0 + ty + 8 * k;
        tile[ty + 8 * k][tx] = x[((size_t)bz * 768 + cd) * 1024 + hw0 + tx];
    }
    __syncthreads();
#pragma unroll
    for (int k = 0; k < 4; k++) {
        int hw = hw0 + ty + 8 * k;
        int cd = cd0 + tx;
        g_t[((size_t)bz * 1024 + hw) * 768 + cd] =
            tfr(tile[tx][ty + 8 * k] + pos[(size_t)hw * 768 + cd]);
    }
}

__global__ void cvt_weights(const float* __restrict__ qkv_w,
                            const float* __restrict__ proj_w) {
    int i = blockIdx.x * 256 + threadIdx.x;
    if (i < 3 * DIM * DIM) g_wq[i] = tfr(qkv_w[i]);
    if (i < DIM * DIM)     g_wp[i] = tfr(proj_w[i]);
}

__global__ void l2_part() {
    int chunk = blockIdx.x, z = blockIdx.y, which = blockIdx.z;
    const float* p = (which ? g_k : g_q) + ((size_t)z * HW + chunk * 128) * DHd;
    int col = threadIdx.x;
    float ss = 0.f;
#pragma unroll 4
    for (int r = 0; r < 128; r++) {
        float v = p[(size_t)r * DHd + col];
        ss += v * v;
    }
    g_part[(((size_t)which * BH + z) * 8 + chunk) * DHd + col] = ss;
}

__global__ void l2_inv() {
    int which = blockIdx.x >> 5, z = blockIdx.x & 31;
    int col = threadIdx.x;
    float ss = 0.f;
#pragma unroll
    for (int c = 0; c < 8; c++)
        ss += g_part[(((size_t)which * BH + z) * 8 + c) * DHd + col];
    g_inv[((size_t)which * BH + z) * DHd + col] = 1.f / fmaxf(sqrtf(ss), 1e-12f);
}

__global__ void l2_scale() {
    int which = blockIdx.z, z = blockIdx.y;
    int i = blockIdx.x * 256 + threadIdx.x;
    int seq = i / 48, c4 = i % 48;
    float* p = (which ? g_k : g_q) + ((size_t)z * HW + seq) * DHd + c4 * 4;
    float4 v  = *reinterpret_cast<float4*>(p);
    float4 iv = *reinterpret_cast<const float4*>(g_inv + ((size_t)which * BH + z) * DHd + c4 * 4);
    v.x = tfr(v.x * iv.x); v.y = tfr(v.y * iv.y);
    v.z = tfr(v.z * iv.z); v.w = tfr(v.w * iv.w);
    *reinterpret_cast<float4*>(p) = v;
}

__global__ void ln_stats() {
    __shared__ float red[256];
    int row = blockIdx.x;
    int tid = threadIdx.x;
    const float* basep = g_proj + (size_t)row * DIM;

    float v[3];
    float s = 0.f;
#pragma unroll
    for (int j = 0; j < 3; j++) { v[j] = basep[tid + 256 * j]; s += v[j]; }
    red[tid] = s; __syncthreads();
    for (int st = 128; st > 0; st >>= 1) {
        if (tid < st) red[tid] += red[tid + st];
        __syncthreads();
    }
    float mu = red[0] * (1.f / DIM); __syncthreads();

    float s2 = 0.f;
#pragma unroll
    for (int j = 0; j < 3; j++) { float d = v[j] - mu; s2 += d * d; }
    red[tid] = s2; __syncthreads();
    for (int st = 128; st > 0; st >>= 1) {
        if (tid < st) red[tid] += red[tid + st];
        __syncthreads();
    }
    if (tid == 0) {
        g_mu[row] = mu;
        g_rs[row] = rsqrtf(red[0] * (1.f / DIM) + 1e-5f);
    }
}

// LN apply + residual + layout restore (smem tile transpose)
__global__ void ln_apply(const float* __restrict__ x,
                         const float* __restrict__ gamma,
                         const float* __restrict__ beta) {
    __shared__ float tile[32][33];
    int bz = blockIdx.z, hw0 = blockIdx.y * 32, cd0 = blockIdx.x * 32;
    int tx = threadIdx.x, ty = threadIdx.y;
#pragma unroll
    for (int k = 0; k < 4; k++) {
        int hw = hw0 + ty + 8 * k;
        int row = bz * 1024 + hw;
        int cd = cd0 + tx;
        float v = g_proj[(size_t)row * 768 + cd];
        tile[ty + 8 * k][tx] = (v - g_mu[row]) * g_rs[row] * gamma[cd] + beta[cd];
    }
    __syncthreads();
#pragma unroll
    for (int k = 0; k < 4; k++) {
        int cd = cd0 + ty + 8 * k;
        int hw = hw0 + tx;
        size_t oi = ((size_t)bz * 768 + cd) * 1024 + hw;
        g_y[oi] = tile[tx][ty + 8 * k] + x[oi];
    }
}

__global__ __launch_bounds__(1024) void dwconv(const float* __restrict__ dw_w,
                                               const float* __restrict__ dw_b) {
    __shared__ float tile[3][34][34];
    __shared__ float wsh[27];
    int bcd = blockIdx.x;
    int d  = bcd & 7;
    int bc = bcd >> 3;
    int c  = bc % Cc;
    int tid = threadIdx.x;

    if (tid < 27) wsh[tid] = dw_w[c * 27 + tid];

    for (int idx = tid; idx < 3 * 34 * 34; idx += 1024) {
        int pl = idx / 1156;
        int r  = (idx - pl * 1156) / 34;
        int cc = idx - pl * 1156 - r * 34;
        int dd = d - 1 + pl, hh = r - 1, ww = cc - 1;
        float val = 0.f;
        if (dd >= 0 && dd < Dd && hh >= 0 && hh < Hh && ww >= 0 && ww < Ww)
            val = g_y[(bc * Dd + dd) * HW + hh * Ww + ww];
        tile[pl][r][cc] = val;
    }
    __syncthreads();

    int h = tid >> 5, w = tid & 31;
    float s = 0.f;
#pragma unroll
    for (int pl = 0; pl < 3; pl++)
#pragma unroll
        for (int i = 0; i < 3; i++)
#pragma unroll
            for (int j = 0; j < 3; j++)
                s += tile[pl][h + i][w + j] * wsh[pl * 9 + i * 3 + j];
    g_z[bcd * HW + tid] = s + dw_b[c];
}

__global__ __launch_bounds__(128) void pwconv(const float* __restrict__ pw_w,
                                              const float* __restrict__ pw_b,
                                              float* __restrict__ out) {
    __shared__ float wsh[Cc * Cc];
    int b = blockIdx.y;
    int pos = blockIdx.x * 128 + threadIdx.x;
    constexpr int SP = Dd * HW;

    for (int i = threadIdx.x; i < Cc * Cc; i += 128) wsh[i] = pw_w[i];
    __syncthreads();

    float acc[Cc];
#pragma unroll
    for (int co = 0; co < Cc; co++) acc[co] = 0.f;

    const float* zb = g_z + b * Cc * SP + pos;
    for (int ci = 0; ci < Cc; ci++) {
        float zv = zb[ci * SP];
#pragma unroll
        for (int co = 0; co < Cc; co++) acc[co] += zv * wsh[co * Cc + ci];
    }

    const float* yb = g_y + b * Cc * SP + pos;
    float* ob = out + b * Cc * SP + pos;
#pragma unroll
    for (int co = 0; co < Cc; co++)
        ob[co * SP] = yb[co * SP] + acc[co] + pw_b[co];
}

// ---------------------------------------------------------------------------
// Launch
// ---------------------------------------------------------------------------
extern "C" void kernel_launch(void* const* d_in, const int* in_sizes, int n_in,
                              void* d_out, int out_size) {
    const float* x      = (const float*)d_in[0];
    const float* pos    = (const float*)d_in[1];
    const float* qkv_w  = (const float*)d_in[2];
    const float* proj_w = (const float*)d_in[3];
    const float* proj_b = (const float*)d_in[4];
    const float* temp   = (const float*)d_in[5];
    const float* ln_g   = (const float*)d_in[6];
    const float* ln_b   = (const float*)d_in[7];
    const float* dw_w   = (const float*)d_in[8];
    const float* dw_b   = (const float*)d_in[9];
    const float* pw_w   = (const float*)d_in[10];
    const float* pw_b   = (const float*)d_in[11];
    float* out = (float*)d_out;

    constexpr int SMEM256 = 3 * (4096 + 8192) * 4;   // 144 KB
    constexpr int FSMEM   = FS_TOT * 4;              // 153 KB
    cudaFuncSetAttribute(tc_gemm<0>, cudaFuncAttributeMaxDynamicSharedMemorySize, SMEM256);
    cudaFuncSetAttribute(tc_gemm<3>, cudaFuncAttributeMaxDynamicSharedMemorySize, SMEM256);
    cudaFuncSetAttribute(flash_attn, cudaFuncAttributeMaxDynamicSharedMemorySize, FSMEM);

    permute_t<<<dim3(24, 32, 8), dim3(32, 8)>>>(x, pos);
    cvt_weights<<<(3 * DIM * DIM + 255) / 256, 256>>>(qkv_w, proj_w);
    tc_gemm<0><<<dim3(9, 64, 1), 512, SMEM256>>>(nullptr);
    l2_part<<<dim3(8, 32, 2), 192>>>();
    l2_inv<<<64, 192>>>();
    l2_scale<<<dim3(192, 32, 2), 256>>>();
    flash_attn<<<dim3(16, 32), 256, FSMEM>>>(temp);
    tc_gemm<3><<<dim3(3, 64, 1), 512, SMEM256>>>(proj_b);
    ln_stats<<<SEQROWS, 256>>>();
    ln_apply<<<dim3(24, 32, 8), dim3(32, 8)>>>(x, ln_g, ln_b);
    dwconv<<<Bn * Cc * Dd, 1024>>>(dw_w, dw_b);
    pwconv<<<dim3(64, Bn, 1), 128>>>(pw_w, pw_b, out);
}